// round 8
// baseline (speedup 1.0000x reference)
#include <cuda_runtime.h>

#define FULL 0xffffffffu
#define BATCH 32768

// Fully fused VQC (R7-validated math): out_i = K_i * sum_T D_i[T] * sigma_T
//   sigma_T = prod_{b in T} sin z_{7-b},  K_i = prod_{b in A_i} cos z_{7-b}
//   D_i = (1/256) * FWHT_w[ cos(phi_w - phi_{w^A_i}) ]   (weights only)
// A = {0x80,0x40,0xA0,0x50,0xA8,0x54,0xAA,0x55}.
// R8 change: 4 threads per element (one output-pair each, warp-uniform j),
// 512 blocks x 256 threads -> 4x concurrency. FWHT per block unchanged.

__global__ __launch_bounds__(256) void vqc_fused(const float* __restrict__ inputs,
                                                 const float* __restrict__ weights,
                                                 float* __restrict__ out) {
    __shared__ float sD[8][256];

    const int tid  = threadIdx.x;
    const int lane = tid & 31;
    const int wid  = tid >> 5;
    const int j    = tid >> 6;                    // output pair (warp-uniform)
    const int e    = blockIdx.x * 64 + (tid & 63);

    // ---- hoisted input load + sincos (overlaps FWHT) ----
    const float4 z0 = *reinterpret_cast<const float4*>(inputs + e * 8);
    const float4 z1 = *reinterpret_cast<const float4*>(inputs + e * 8 + 4);
    float sz0, cz0, sz1, cz1, sz2, cz2, sz3, cz3, sz4, cz4, sz5, cz5, sz6, cz6, sz7, cz7;
    __sincosf(z0.x, &sz0, &cz0);  __sincosf(z0.y, &sz1, &cz1);
    __sincosf(z0.z, &sz2, &cz2);  __sincosf(z0.w, &sz3, &cz3);
    __sincosf(z1.x, &sz4, &cz4);  __sincosf(z1.y, &sz5, &cz5);
    __sincosf(z1.z, &sz6, &cz6);  __sincosf(z1.w, &sz7, &cz7);

    // ---- per-warp FWHT: warp `wid` builds table D_wid (validated R5-R7) ----
    {
        const int i  = wid;
        const int sh = 6 - 2 * (i >> 1);
        const int A  = (((0xAA >> sh) << sh) >> (i & 1));

        const int msk[16]  = {0x01,0x03,0x06,0x0C,0x18,0x30,0x60,0xC0,
                              0x01,0x02,0x05,0x0A,0x14,0x28,0x50,0xA0};
        const int widx[16] = {7,6,5,4,3,2,1,0, 15,14,13,12,11,10,9,8};

        float C[8];
#pragma unroll
        for (int r = 0; r < 8; r++) {
            const int w = r * 32 + lane;
            float d = 0.0f;
#pragma unroll
            for (int jj = 0; jj < 16; jj++) {
                if (__popc(msk[jj] & A) & 1) {               // warp-uniform
                    float th = __ldg(&weights[widx[jj]]);
                    d += (__popc(msk[jj] & w) & 1) ? -th : th;
                }
            }
            C[r] = __cosf(d);
        }
#pragma unroll
        for (int sb = 1; sb < 8; sb <<= 1) {
            float t[8];
#pragma unroll
            for (int r = 0; r < 8; r++)
                t[r] = (r & sb) ? (C[r ^ sb] - C[r]) : (C[r] + C[r ^ sb]);
#pragma unroll
            for (int r = 0; r < 8; r++) C[r] = t[r];
        }
#pragma unroll
        for (int s = 1; s < 32; s <<= 1) {
            float sign = (lane & s) ? -1.0f : 1.0f;
#pragma unroll
            for (int r = 0; r < 8; r++) {
                float o = __shfl_xor_sync(FULL, C[r], s);
                C[r] = fmaf(sign, C[r], o);
            }
        }
#pragma unroll
        for (int r = 0; r < 8; r++)
            sD[i][r * 32 + lane] = C[r] * (1.0f / 256.0f);
    }
    __syncthreads();

    // ---- evaluation: thread computes outputs {2j, 2j+1} for element e ----
    float2 res;

    if (j == 0) {
        float K0 = cz0, K1 = cz1;
        float o0 = K0 * fmaf(sD[0][0x60], sz2 * sz1, sD[0][0x00]);
        float o1 = fmaf(sD[1][0xA0], sz2 * sz0, sD[1][0x00]);
        o1 = fmaf(sD[1][0x30], sz3 * sz2, o1);
        o1 = fmaf(sD[1][0x90], sz3 * sz0, o1);
        o1 *= K1;
        res = make_float2(o0, o1);
    } else if (j == 1) {
        float K2 = cz0 * cz2, K3 = cz1 * cz3;
        float o2 = fmaf(sD[2][0x50], sz3 * sz1, sD[2][0x00]);
        o2 = fmaf(sD[2][0x18], sz4 * sz3, o2);
        o2 = fmaf(sD[2][0x48], sz4 * sz1, o2);
        o2 *= K2;
        float s0C = sz5 * sz4;
        float s20 = sz2 * sz0;
        float o3 = fmaf(sD[3][0x28], sz4 * sz2, sD[3][0x00]);
        o3 = fmaf(sD[3][0x0C], s0C, o3);
        o3 = fmaf(sD[3][0x24], sz5 * sz2, o3);
        o3 = fmaf(sD[3][0xA0], s20, o3);
        o3 = fmaf(sD[3][0x84], sz5 * sz0, o3);
        o3 = fmaf(sD[3][0xAC], s0C * s20, o3);
        o3 = fmaf(sD[3][0x88], sz4 * sz0, o3);
        o3 *= K3;
        res = make_float2(o2, o3);
    } else if (j == 2) {
        float K4 = cz0 * cz2 * cz4, K5 = cz1 * cz3 * cz5;
        float s42 = sz4 * sz2, s40 = sz4 * sz0, s20 = sz2 * sz0, s420 = s42 * sz0;
        float m31 = sz3 * sz1;
        float p8[8] = {1.0f, sz4, sz2, s42, sz0, s40, s20, s420};
        float p4[4] = {1.0f, sz3, sz1, m31};

        const int b4[4] = {0, 16, 64, 80};
        float acc4 = 0.0f;
#pragma unroll
        for (int g = 0; g < 4; g++) {
            float4 a = *reinterpret_cast<const float4*>(&sD[4][b4[g]]);
            float4 b = *reinterpret_cast<const float4*>(&sD[4][b4[g] + 4]);
            float lo = fmaf(a.y, sz7, a.x) + sz6 * fmaf(a.w, sz7, a.z);
            float hi = fmaf(b.y, sz7, b.x) + sz6 * fmaf(b.w, sz7, b.z);
            acc4 = fmaf(p4[g], fmaf(sz5, hi, lo), acc4);
        }
        const int b5[8] = {0, 8, 32, 40, 128, 136, 160, 168};
        float acc5 = 0.0f;
#pragma unroll
        for (int g = 0; g < 8; g++) {
            float4 a = *reinterpret_cast<const float4*>(&sD[5][b5[g]]);
            float inner = fmaf(a.y, sz7, a.x) + sz6 * fmaf(a.w, sz7, a.z);
            acc5 = fmaf(p8[g], inner, acc5);
        }
        res = make_float2(K4 * acc4, K5 * acc5);
    } else {
        float K6 = cz0 * cz2 * cz4 * cz6, K7 = cz1 * cz3 * cz5 * cz7;
        float s42 = sz4 * sz2, s40 = sz4 * sz0, s20 = sz2 * sz0, s420 = s42 * sz0;
        float m53 = sz5 * sz3, m51 = sz5 * sz1, m31 = sz3 * sz1, m531 = m53 * sz1;
        float p8[8] = {1.0f, sz4, sz2, s42, sz0, s40, s20, s420};
        float p6[8] = {1.0f, sz5, sz3, m53, sz1, m51, m31, m531};

        const int b6[8] = {0, 4, 16, 20, 64, 68, 80, 84};
        float acc6 = 0.0f;
#pragma unroll
        for (int g = 0; g < 8; g++) {
            float2 a = *reinterpret_cast<const float2*>(&sD[6][b6[g]]);
            acc6 = fmaf(p6[g], fmaf(a.y, sz7, a.x), acc6);
        }
        const int b5[8] = {0, 8, 32, 40, 128, 136, 160, 168};
        float acc7 = 0.0f;
#pragma unroll
        for (int g = 0; g < 8; g++) {
            float lo = sD[7][b5[g]];
            float hi = sD[7][b5[g] + 2];
            acc7 = fmaf(p8[g], fmaf(hi, sz6, lo), acc7);
        }
        res = make_float2(K6 * acc6, K7 * acc7);
    }

    *reinterpret_cast<float2*>(out + e * 8 + 2 * j) = res;
}

extern "C" void kernel_launch(void* const* d_in, const int* in_sizes, int n_in,
                              void* d_out, int out_size) {
    const float* inputs  = (const float*)d_in[0];   // (32768, 8) float32
    const float* weights = (const float*)d_in[1];   // (2, 8)     float32
    float* out = (float*)d_out;                     // (32768, 8) float32

    // 512 blocks x 256 threads: 64 elements/block, 4 threads/element
    vqc_fused<<<BATCH / 64, 256>>>(inputs, weights, out);
}

// round 9
// speedup vs baseline: 1.6311x; 1.6311x over previous
#include <cuda_runtime.h>

#define FULL 0xffffffffu
#define BATCH 32768

// Fused VQC (math validated R7): out_i = K_i * sum_T D_i[T] * sigma_T.
// R9: 512-thread blocks, 256 elements/block. Two threads per element with
// warp-uniform roles (tid>>8): role 0 = angles 0-3 + outputs 0-4 (+FWHT in
// warps 0-7); role 1 = angles 4-7 + outputs 5-7. Sincos halves exchanged via
// conflict-free smem. Total LDG/MUFU/FWHT work identical to R7; 2x warps.

__global__ __launch_bounds__(512) void vqc_fused(const float* __restrict__ inputs,
                                                 const float* __restrict__ weights,
                                                 float* __restrict__ out) {
    __shared__ float sD[8][256];
    __shared__ float s_sz[8][256];
    __shared__ float s_cz[5][256];

    const int tid  = threadIdx.x;
    const int lane = tid & 31;
    const int wid  = tid >> 5;
    const int role = tid >> 8;          // warp-uniform
    const int eloc = tid & 255;
    const int e    = blockIdx.x * 256 + eloc;

    // weights preload for FWHT warps (hoists L2/DRAM latency)
    float th[16];
    if (wid < 8) {
        const int widx[16] = {7,6,5,4,3,2,1,0, 15,14,13,12,11,10,9,8};
#pragma unroll
        for (int j = 0; j < 16; j++) th[j] = __ldg(&weights[widx[j]]);
    }

    // each thread loads its half-element: angles role*4 .. role*4+3
    const float4 zz = *reinterpret_cast<const float4*>(inputs + e * 8 + role * 4);
    float sA, cA, sB, cB, sC, cC, sE, cE;
    __sincosf(zz.x, &sA, &cA);  __sincosf(zz.y, &sB, &cB);
    __sincosf(zz.z, &sC, &cC);  __sincosf(zz.w, &sE, &cE);

    // publish sincos halves (4B stride -> conflict-free)
    if (role == 0) {                      // owns sz0..3, cz0..3
        s_sz[0][eloc] = sA; s_sz[1][eloc] = sB; s_sz[2][eloc] = sC; s_sz[3][eloc] = sE;
        s_cz[0][eloc] = cA; s_cz[1][eloc] = cB; s_cz[2][eloc] = cC; s_cz[3][eloc] = cE;
    } else {                              // owns sz4..7, cz4..7
        s_sz[4][eloc] = sA; s_sz[5][eloc] = sB; s_sz[6][eloc] = sC; s_sz[7][eloc] = sE;
        s_cz[4][eloc] = cA;
    }

    // ---- per-warp FWHT (warps 0-7), byte-identical math to R7 ----
    if (wid < 8) {
        const int i  = wid;
        const int sh = 6 - 2 * (i >> 1);
        const int A  = (((0xAA >> sh) << sh) >> (i & 1));
        const int msk[16] = {0x01,0x03,0x06,0x0C,0x18,0x30,0x60,0xC0,
                             0x01,0x02,0x05,0x0A,0x14,0x28,0x50,0xA0};
        float C[8];
#pragma unroll
        for (int r = 0; r < 8; r++) {
            const int w = r * 32 + lane;
            float d = 0.0f;
#pragma unroll
            for (int jj = 0; jj < 16; jj++) {
                if (__popc(msk[jj] & A) & 1)                 // warp-uniform
                    d += (__popc(msk[jj] & w) & 1) ? -th[jj] : th[jj];
            }
            C[r] = __cosf(d);
        }
#pragma unroll
        for (int sb = 1; sb < 8; sb <<= 1) {
            float t[8];
#pragma unroll
            for (int r = 0; r < 8; r++)
                t[r] = (r & sb) ? (C[r ^ sb] - C[r]) : (C[r] + C[r ^ sb]);
#pragma unroll
            for (int r = 0; r < 8; r++) C[r] = t[r];
        }
#pragma unroll
        for (int s = 1; s < 32; s <<= 1) {
            float sign = (lane & s) ? -1.0f : 1.0f;
#pragma unroll
            for (int r = 0; r < 8; r++) {
                float o = __shfl_xor_sync(FULL, C[r], s);
                C[r] = fmaf(sign, C[r], o);
            }
        }
#pragma unroll
        for (int r = 0; r < 8; r++)
            sD[i][r * 32 + lane] = C[r] * (1.0f / 256.0f);
    }
    __syncthreads();

    if (role == 0) {
        // own: sz0-3 = sA..sE, cz0-3 = cA..cE ; fetch sz4-7, cz4
        const float sz0 = sA, sz1 = sB, sz2 = sC, sz3 = sE;
        const float cz0 = cA, cz1 = cB, cz2 = cC, cz3 = cE;
        const float sz4 = s_sz[4][eloc], sz5 = s_sz[5][eloc];
        const float sz6 = s_sz[6][eloc], sz7 = s_sz[7][eloc];
        const float cz4 = s_cz[4][eloc];

        float o0 = cz0 * fmaf(sD[0][0x60], sz2 * sz1, sD[0][0x00]);

        float o1 = fmaf(sD[1][0xA0], sz2 * sz0, sD[1][0x00]);
        o1 = fmaf(sD[1][0x30], sz3 * sz2, o1);
        o1 = fmaf(sD[1][0x90], sz3 * sz0, o1);
        o1 *= cz1;

        float o2 = fmaf(sD[2][0x50], sz3 * sz1, sD[2][0x00]);
        o2 = fmaf(sD[2][0x18], sz4 * sz3, o2);
        o2 = fmaf(sD[2][0x48], sz4 * sz1, o2);
        o2 *= cz0 * cz2;

        float s0C = sz5 * sz4, s20 = sz2 * sz0;
        float o3 = fmaf(sD[3][0x28], sz4 * sz2, sD[3][0x00]);
        o3 = fmaf(sD[3][0x0C], s0C, o3);
        o3 = fmaf(sD[3][0x24], sz5 * sz2, o3);
        o3 = fmaf(sD[3][0xA0], s20, o3);
        o3 = fmaf(sD[3][0x84], sz5 * sz0, o3);
        o3 = fmaf(sD[3][0xAC], s0C * s20, o3);
        o3 = fmaf(sD[3][0x88], sz4 * sz0, o3);
        o3 *= cz1 * cz3;

        // out4: comp(0xA8); inner sz7,sz6,sz5; outer p4 = {1,sz3,sz1,sz3*sz1}
        float p4[4] = {1.0f, sz3, sz1, sz3 * sz1};
        const int b4[4] = {0, 16, 64, 80};
        float acc4 = 0.0f;
#pragma unroll
        for (int g = 0; g < 4; g++) {
            float4 a = *reinterpret_cast<const float4*>(&sD[4][b4[g]]);
            float4 b = *reinterpret_cast<const float4*>(&sD[4][b4[g] + 4]);
            float lo = fmaf(a.y, sz7, a.x) + sz6 * fmaf(a.w, sz7, a.z);
            float hi = fmaf(b.y, sz7, b.x) + sz6 * fmaf(b.w, sz7, b.z);
            acc4 = fmaf(p4[g], fmaf(sz5, hi, lo), acc4);
        }
        float o4 = (cz0 * cz2 * cz4) * acc4;

        *reinterpret_cast<float4*>(out + e * 8) = make_float4(o0, o1, o2, o3);
        out[e * 8 + 4] = o4;
    } else {
        // own: sz4-7 = sA..sE, cz4-7 = cA..cE ; fetch sz0-3, cz0-3
        const float sz4 = sA, sz5 = sB, sz6 = sC, sz7 = sE;
        const float cz4 = cA, cz5 = cB, cz6 = cC, cz7 = cE;
        const float sz0 = s_sz[0][eloc], sz1 = s_sz[1][eloc];
        const float sz2 = s_sz[2][eloc], sz3 = s_sz[3][eloc];
        const float cz0 = s_cz[0][eloc], cz1 = s_cz[1][eloc];
        const float cz2 = s_cz[2][eloc], cz3 = s_cz[3][eloc];

        float s42 = sz4 * sz2, s40 = sz4 * sz0, s20 = sz2 * sz0, s420 = s42 * sz0;
        float m53 = sz5 * sz3, m51 = sz5 * sz1, m31 = sz3 * sz1, m531 = m53 * sz1;
        float p8[8] = {1.0f, sz4, sz2, s42, sz0, s40, s20, s420};
        float p6[8] = {1.0f, sz5, sz3, m53, sz1, m51, m31, m531};

        const int b5[8] = {0, 8, 32, 40, 128, 136, 160, 168};
        float acc5 = 0.0f;
#pragma unroll
        for (int g = 0; g < 8; g++) {
            float4 a = *reinterpret_cast<const float4*>(&sD[5][b5[g]]);
            float inner = fmaf(a.y, sz7, a.x) + sz6 * fmaf(a.w, sz7, a.z);
            acc5 = fmaf(p8[g], inner, acc5);
        }
        const int b6[8] = {0, 4, 16, 20, 64, 68, 80, 84};
        float acc6 = 0.0f;
#pragma unroll
        for (int g = 0; g < 8; g++) {
            float2 a = *reinterpret_cast<const float2*>(&sD[6][b6[g]]);
            acc6 = fmaf(p6[g], fmaf(a.y, sz7, a.x), acc6);
        }
        float acc7 = 0.0f;
#pragma unroll
        for (int g = 0; g < 8; g++) {
            float lo = sD[7][b5[g]];
            float hi = sD[7][b5[g] + 2];
            acc7 = fmaf(p8[g], fmaf(hi, sz6, lo), acc7);
        }

        float o5 = (cz1 * cz3 * cz5) * acc5;
        float o6 = (cz0 * cz2 * cz4 * cz6) * acc6;
        float o7 = (cz1 * cz3 * cz5 * cz7) * acc7;

        out[e * 8 + 5] = o5;
        *reinterpret_cast<float2*>(out + e * 8 + 6) = make_float2(o6, o7);
    }
}

extern "C" void kernel_launch(void* const* d_in, const int* in_sizes, int n_in,
                              void* d_out, int out_size) {
    const float* inputs  = (const float*)d_in[0];   // (32768, 8) float32
    const float* weights = (const float*)d_in[1];   // (2, 8)     float32
    float* out = (float*)d_out;                     // (32768, 8) float32

    // 128 blocks x 512 threads: 256 elements/block, 2 threads/element
    vqc_fused<<<BATCH / 256, 512>>>(inputs, weights, out);
}